// round 2
// baseline (speedup 1.0000x reference)
#include <cuda_runtime.h>
#include <math.h>

#define NT    512
#define NBLK  592
#define BATCH 50000
#define NPAIR ((BATCH + 1) / 2)

// ---- shared memory layout (float offsets) ----
#define OFF_SFT  0            // sft[k][p]  45 x 91 (pad)
#define OFF_ISFT 4095         // isft[p][k] 90 x 47 (pad)
#define OFF_SC   8325         // scale[45] (+pad)
#define OFF_W    8373         // all weights, padded rows (26404 floats)
#define OFF_A    34777        // x buffer  [2][64][49]
#define OFF_B    41049        // t buffer  [2][64][49]
#define OFF_SIG  47321        // sig       [2][32][91]
#define SMEM_FLOATS 53145
#define SMEM_BYTES  (SMEM_FLOATS * 4)

// per-layer weight offsets inside OFF_W, row stride RS = Cin*5 + 1 (odd, bank-friendly)
#define WOFF1 0        // 16 x 21
#define WOFF2 336      // 32 x 81
#define WOFF3 2928     // 64 x 161
#define WOFF4 13232    // 32 x 321
#define WOFF5 23504    // 16 x 161
#define WOFF6 26080    // 4  x 81
// total 26404

static_assert(OFF_SIG + 2 * 32 * 91 == SMEM_FLOATS, "smem layout");

// 15 k-tiles aligned to degree-group boundaries: each tile has a single ls_idx d
__constant__ int c_tk0[15] = {0, 1, 5, 6, 10, 14, 15, 19, 23, 27, 28, 32, 36, 40, 44};
__constant__ int c_tkl[15] = {1, 4, 1, 4, 4, 1, 4, 4, 4, 1, 4, 4, 4, 4, 1};
__constant__ int c_td[15]  = {0, 1, 1, 2, 2, 2, 3, 3, 3, 3, 4, 4, 4, 4, 4};

// sconv: t[bi][o][k] = scale[k] * sum_c x[bi][c][k] * W[o][c][d(k)]
template <int Cin, int Cout, int WOFF, int RS>
__device__ __forceinline__ void sconv_step(float* sm, int tid)
{
    constexpr int NO4 = Cout / 4;
    constexpr int SLOTS = 2 * NO4 * 15;
    if (tid < SLOTS) {
        const int kt = tid % 15;
        const int bi = (tid / 15) & 1;
        const int ot = tid / 30;
        const int k0   = c_tk0[kt];
        const int klen = c_tkl[kt];
        const int d    = c_td[kt];
        const float* __restrict__ A = sm + OFF_A + (bi * 64) * 49 + k0;
        const float* __restrict__ W = sm + OFF_W + WOFF + (ot * 4) * RS + d;

        float acc[4][4];
#pragma unroll
        for (int i = 0; i < 4; i++)
#pragma unroll
            for (int j = 0; j < 4; j++) acc[i][j] = 0.f;

#pragma unroll 4
        for (int c = 0; c < Cin; c++) {
            float xv[4];
#pragma unroll
            for (int j = 0; j < 4; j++) xv[j] = A[c * 49 + j];   // k0+3 <= 47 < 49: safe
#pragma unroll
            for (int i = 0; i < 4; i++) {
                float w = W[i * RS + c * 5];
#pragma unroll
                for (int j = 0; j < 4; j++) acc[i][j] = fmaf(w, xv[j], acc[i][j]);
            }
        }

        float* __restrict__ B = sm + OFF_B + (bi * 64 + ot * 4) * 49 + k0;
#pragma unroll
        for (int i = 0; i < 4; i++)
#pragma unroll
            for (int j = 0; j < 4; j++)
                if (j < klen) B[i * 49 + j] = acc[i][j] * sm[OFF_SC + k0 + j];
    }
}

// GEMM1: sig[bi][c-ch0][p] = relu( sum_k isft[p][k] * t[bi][c][k] )
template <int CH>
__device__ __forceinline__ void gemm1_step(float* sm, int ch0, int tid)
{
    constexpr int NC4 = CH / 4;
    constexpr int SLOTS = 2 * NC4 * 15;
    if (tid < SLOTS) {
        const int pt = tid % 15;
        const int bi = (tid / 15) & 1;
        const int ct = tid / 30;
        const float* __restrict__ T  = sm + OFF_B + (bi * 64 + ch0 + ct * 4) * 49;
        const float* __restrict__ IS = sm + OFF_ISFT + (pt * 6) * 47;

        float acc[4][6];
#pragma unroll
        for (int i = 0; i < 4; i++)
#pragma unroll
            for (int j = 0; j < 6; j++) acc[i][j] = 0.f;

#pragma unroll 5
        for (int k = 0; k < 45; k++) {
            float xv[4], iv[6];
#pragma unroll
            for (int i = 0; i < 4; i++) xv[i] = T[i * 49 + k];
#pragma unroll
            for (int j = 0; j < 6; j++) iv[j] = IS[j * 47 + k];
#pragma unroll
            for (int i = 0; i < 4; i++)
#pragma unroll
                for (int j = 0; j < 6; j++) acc[i][j] = fmaf(xv[i], iv[j], acc[i][j]);
        }

        float* __restrict__ S = sm + OFF_SIG + (bi * 32 + ct * 4) * 91 + pt * 6;
#pragma unroll
        for (int i = 0; i < 4; i++)
#pragma unroll
            for (int j = 0; j < 6; j++) S[i * 91 + j] = fmaxf(acc[i][j], 0.f);
    }
}

// GEMM2: x[bi][c][k] = sum_p sft[k][p] * sig[bi][c-ch0][p]
template <int CH>
__device__ __forceinline__ void gemm2_step(float* sm, int ch0, int tid)
{
    constexpr int NC4 = CH / 4;
    constexpr int SLOTS = 2 * NC4 * 15;
    if (tid < SLOTS) {
        const int kt = tid % 15;
        const int bi = (tid / 15) & 1;
        const int ct = tid / 30;
        const int k0 = kt * 3;
        const float* __restrict__ S = sm + OFF_SIG + (bi * 32 + ct * 4) * 91;
        const float* __restrict__ F = sm + OFF_SFT + k0 * 91;

        float acc[4][3];
#pragma unroll
        for (int i = 0; i < 4; i++)
#pragma unroll
            for (int j = 0; j < 3; j++) acc[i][j] = 0.f;

#pragma unroll 5
        for (int p = 0; p < 90; p++) {
            float sv[4], fv[3];
#pragma unroll
            for (int i = 0; i < 4; i++) sv[i] = S[i * 91 + p];
#pragma unroll
            for (int j = 0; j < 3; j++) fv[j] = F[j * 91 + p];
#pragma unroll
            for (int i = 0; i < 4; i++)
#pragma unroll
                for (int j = 0; j < 3; j++) acc[i][j] = fmaf(sv[i], fv[j], acc[i][j]);
        }

        float* __restrict__ A = sm + OFF_A + (bi * 64 + ch0 + ct * 4) * 49 + k0;
#pragma unroll
        for (int i = 0; i < 4; i++)
#pragma unroll
            for (int j = 0; j < 3; j++) A[i * 49 + j] = acc[i][j];
    }
}

template <int Cin, int Cout, int WOFF, int RS>
__device__ __forceinline__ void run_layer(float* sm, int tid)
{
    sconv_step<Cin, Cout, WOFF, RS>(sm, tid);
    __syncthreads();
    constexpr int CH = (Cout < 32) ? Cout : 32;
#pragma unroll
    for (int ch0 = 0; ch0 < Cout; ch0 += 32) {
        gemm1_step<CH>(sm, ch0, tid);
        __syncthreads();
        gemm2_step<CH>(sm, ch0, tid);
        __syncthreads();
    }
}

__device__ __forceinline__ void stage_w(float* dst, const float* __restrict__ g,
                                        int Cout, int Cin, int rs, int tid)
{
    const int row = Cin * 5;
    const int n = Cout * row;
    for (int i = tid; i < n; i += NT) {
        int o = i / row;
        int r = i - o * row;
        dst[o * rs + r] = g[i];
    }
}

extern "C" __global__ void __launch_bounds__(NT, 1)
scnn_kernel(const float* __restrict__ x, const float* __restrict__ sft,
            const float* __restrict__ isft,
            const float* __restrict__ w1, const float* __restrict__ w2,
            const float* __restrict__ w3, const float* __restrict__ w4,
            const float* __restrict__ w5, const float* __restrict__ w6,
            float* __restrict__ out)
{
    extern __shared__ float sm[];
    const int tid = threadIdx.x;

    // ---- stage static operands once per block ----
    for (int i = tid; i < 45 * 90; i += NT) {
        int k = i / 90, p = i - k * 90;
        sm[OFF_SFT + k * 91 + p] = sft[i];
    }
    for (int i = tid; i < 90 * 45; i += NT) {
        int p = i / 45, k = i - p * 45;
        sm[OFF_ISFT + p * 47 + k] = isft[i];
    }
    if (tid < 45) {
        int k = tid;
        int d = (k >= 28) ? 4 : (k >= 15) ? 3 : (k >= 6) ? 2 : (k >= 1) ? 1 : 0;
        sm[OFF_SC + k] = sqrtf(3.14159265358979323846f / (float)(4 * d + 1));
    }
    stage_w(sm + OFF_W + WOFF1, w1, 16, 4, 21, tid);
    stage_w(sm + OFF_W + WOFF2, w2, 32, 16, 81, tid);
    stage_w(sm + OFF_W + WOFF3, w3, 64, 32, 161, tid);
    stage_w(sm + OFF_W + WOFF4, w4, 32, 64, 321, tid);
    stage_w(sm + OFF_W + WOFF5, w5, 16, 32, 161, tid);
    stage_w(sm + OFF_W + WOFF6, w6, 4, 16, 81, tid);
    __syncthreads();

    // ---- persistent stride loop over batch pairs ----
    for (int pair = blockIdx.x; pair < NPAIR; pair += gridDim.x) {
        const int b0 = pair * 2;

        // load x for 2 batch elements: [2][4][45]
        for (int i = tid; i < 360; i += NT) {
            int bi = i / 180, r = i - bi * 180;
            int c = r / 45, k = r - c * 45;
            int b = b0 + bi;
            sm[OFF_A + (bi * 64 + c) * 49 + k] = (b < BATCH) ? x[b * 180 + r] : 0.f;
        }
        __syncthreads();

        run_layer<4,  16, WOFF1, 21 >(sm, tid);
        run_layer<16, 32, WOFF2, 81 >(sm, tid);
        run_layer<32, 64, WOFF3, 161>(sm, tid);
        run_layer<64, 32, WOFF4, 321>(sm, tid);
        run_layer<32, 16, WOFF5, 161>(sm, tid);
        run_layer<16, 4,  WOFF6, 81 >(sm, tid);

        // store output: [2][4][45]
        for (int i = tid; i < 360; i += NT) {
            int bi = i / 180, r = i - bi * 180;
            int c = r / 45, k = r - c * 45;
            int b = b0 + bi;
            if (b < BATCH) out[b * 180 + r] = sm[OFF_A + (bi * 64 + c) * 49 + k];
        }
        __syncthreads();   // protect bufA before next iteration's load
    }
}

extern "C" void kernel_launch(void* const* d_in, const int* in_sizes, int n_in,
                              void* d_out, int out_size)
{
    cudaFuncSetAttribute(scnn_kernel, cudaFuncAttributeMaxDynamicSharedMemorySize,
                         SMEM_BYTES);
    scnn_kernel<<<NBLK, NT, SMEM_BYTES>>>(
        (const float*)d_in[0], (const float*)d_in[1], (const float*)d_in[2],
        (const float*)d_in[3], (const float*)d_in[4], (const float*)d_in[5],
        (const float*)d_in[6], (const float*)d_in[7], (const float*)d_in[8],
        (float*)d_out);
}